// round 4
// baseline (speedup 1.0000x reference)
#include <cuda_runtime.h>
#include <cstdint>

#define B 8192
#define TC 128                 // tile cols
#define TR 256                 // tile rows
#define GX (B / TC)            // 64
#define GY (B / TR)            // 32
#define NBLK (GX * GY)         // 2048

#define NEG_INF __int_as_float(0xff800000)
#define ENC_OFF 0x007FFFFFu    // enc(-inf); shifted so encoded -inf == 0

// Zero-initialized device scratch. enc2(-inf)==0, so zero-init == "-inf";
// the last block re-zeros everything for the next graph replay.
__device__ unsigned g_rowmax[B];
__device__ unsigned g_colmax[B];
__device__ float    g_diag[B];
__device__ unsigned g_done;

// Monotone float<->uint encoding (shifted): atomicMax(unsigned) == float max.
__device__ __forceinline__ unsigned enc2(float f) {
    unsigned u = __float_as_uint(f);
    return (u ^ ((unsigned)((int)u >> 31) | 0x80000000u)) - ENC_OFF;
}
__device__ __forceinline__ float dec2(unsigned e) {
    unsigned x = e + ENC_OFF;
    unsigned u = (x & 0x80000000u) ? (x ^ 0x80000000u) : ~x;
    return __uint_as_float(u);
}

// Scan body: each warp handles 2 rows per iteration (MLP=2), 16 iterations.
template<bool DIAG>
__device__ __forceinline__ void scan_body(const float* __restrict__ sim,
                                          int rowBase, int colBase,
                                          int tx, int ty, float* cm) {
    const int gcol = colBase + tx * 4;
    for (int r = ty * 2; r < TR; r += 16) {
        const int grow = rowBase + r;
        const float4 v0 = *reinterpret_cast<const float4*>(
            sim + (size_t)grow * B + gcol);
        const float4 v1 = *reinterpret_cast<const float4*>(
            sim + (size_t)(grow + 1) * B + gcol);

        float a0 = v0.x, a1 = v0.y, a2 = v0.z, a3 = v0.w;
        float b0 = v1.x, b1 = v1.y, b2 = v1.z, b3 = v1.w;
        if (DIAG) {
            if (grow == gcol + 0) { g_diag[grow] = a0; a0 = NEG_INF; }
            if (grow == gcol + 1) { g_diag[grow] = a1; a1 = NEG_INF; }
            if (grow == gcol + 2) { g_diag[grow] = a2; a2 = NEG_INF; }
            if (grow == gcol + 3) { g_diag[grow] = a3; a3 = NEG_INF; }
            const int g1 = grow + 1;
            if (g1 == gcol + 0) { g_diag[g1] = b0; b0 = NEG_INF; }
            if (g1 == gcol + 1) { g_diag[g1] = b1; b1 = NEG_INF; }
            if (g1 == gcol + 2) { g_diag[g1] = b2; b2 = NEG_INF; }
            if (g1 == gcol + 3) { g_diag[g1] = b3; b3 = NEG_INF; }
        }

        cm[0] = fmaxf(cm[0], fmaxf(a0, b0));
        cm[1] = fmaxf(cm[1], fmaxf(a1, b1));
        cm[2] = fmaxf(cm[2], fmaxf(a2, b2));
        cm[3] = fmaxf(cm[3], fmaxf(a3, b3));

        float ra = fmaxf(fmaxf(a0, a1), fmaxf(a2, a3));   // row r
        float rb = fmaxf(fmaxf(b0, b1), fmaxf(b2, b3));   // row r+1

        // Paired reduce: xor-16 each, pack into half-warps, 4 more steps.
        ra = fmaxf(ra, __shfl_xor_sync(0xffffffffu, ra, 16));
        rb = fmaxf(rb, __shfl_xor_sync(0xffffffffu, rb, 16));
        float c = (tx < 16) ? ra : rb;
        #pragma unroll
        for (int o = 8; o > 0; o >>= 1)
            c = fmaxf(c, __shfl_xor_sync(0xffffffffu, c, o));
        // lane 0 has full max of row r; lane 16 has full max of row r+1.
        if (tx == 0)  atomicMax(&g_rowmax[grow],     enc2(c));
        if (tx == 16) atomicMax(&g_rowmax[grow + 1], enc2(c));
    }
}

__global__ void __launch_bounds__(256, 8) wtl_fused(const float* __restrict__ sim,
                                                    float* __restrict__ out) {
    const int tx = threadIdx.x;            // 0..31
    const int ty = threadIdx.y;            // 0..7
    const int tid = ty * 32 + tx;
    const int colBase = blockIdx.x * TC;
    const int rowBase = blockIdx.y * TR;

    float cm[4];
    cm[0] = cm[1] = cm[2] = cm[3] = NEG_INF;

    // Diagonal intersects this tile iff bx/2 == by (TC=128, TR=256).
    if ((blockIdx.x >> 1) == blockIdx.y)
        scan_body<true >(sim, rowBase, colBase, tx, ty, cm);
    else
        scan_body<false>(sim, rowBase, colBase, tx, ty, cm);

    // Column-max: fold 8 warp-rows via shared, one RED.MAX per column.
    __shared__ float s_col[8][TC];
    *reinterpret_cast<float4*>(&s_col[ty][tx * 4]) =
        make_float4(cm[0], cm[1], cm[2], cm[3]);
    __syncthreads();

    if (tid < TC) {
        float m = s_col[0][tid];
        #pragma unroll
        for (int s = 1; s < 8; s++) m = fmaxf(m, s_col[s][tid]);
        atomicMax(&g_colmax[colBase + tid], enc2(m));
    }

    // ---- completion: last block computes the loss and resets scratch ----
    __shared__ unsigned s_last;
    __threadfence();
    __syncthreads();
    if (tid == 0) s_last = atomicAdd(&g_done, 1u);
    __syncthreads();
    if (s_last != NBLK - 1) return;
    __threadfence();   // acquire: see all other blocks' RED results

    float local = 0.0f;
    for (int i = tid; i < B; i += 256) {
        const float rm  = dec2(__ldcg(&g_rowmax[i]));
        const float cx  = dec2(__ldcg(&g_colmax[i]));
        const float pos = __ldcg(&g_diag[i]);

        const float pos_loss = fmaxf(0.2f * pos * pos - 0.7f * pos + 0.5f, 0.0f);
        if (rm + 1.0f > pos)
            local += pos_loss + fmaxf(0.9f * rm * rm - 0.4f * rm + 0.03f, 0.0f);
        if (cx + 1.0f > pos)
            local += pos_loss + fmaxf(0.9f * cx * cx - 0.4f * cx + 0.03f, 0.0f);

        g_rowmax[i] = 0u;   // reset for next graph replay
        g_colmax[i] = 0u;
    }

    // deterministic block reduction (fixed tree)
    __shared__ float s_sum[256];
    s_sum[tid] = local;
    __syncthreads();
    #pragma unroll
    for (int s = 128; s > 0; s >>= 1) {
        if (tid < s) s_sum[tid] += s_sum[tid + s];
        __syncthreads();
    }
    if (tid == 0) {
        out[0] = s_sum[0] / (float)B;
        g_done = 0u;
    }
}

extern "C" void kernel_launch(void* const* d_in, const int* in_sizes, int n_in,
                              void* d_out, int out_size) {
    const float* sim = (const float*)d_in[0];
    float* out = (float*)d_out;

    dim3 grid(GX, GY);         // (64, 32)
    dim3 block(32, 8);
    wtl_fused<<<grid, block>>>(sim, out);
}

// round 5
// speedup vs baseline: 1.0085x; 1.0085x over previous
#include <cuda_runtime.h>
#include <cstdint>

#define B 8192
#define TC 128                 // tile cols
#define TR 256                 // tile rows
#define GX (B / TC)            // 64
#define GY (B / TR)            // 32
#define NBLK (GX * GY)         // 2048

#define NEG_INF __int_as_float(0xff800000)
#define ENC_OFF 0x007FFFFFu    // enc(-inf); shifted so encoded -inf == 0

// Zero-initialized device scratch. enc2(-inf)==0, so zero-init == "-inf";
// the last block re-zeros everything for the next graph replay.
__device__ unsigned g_rowmax[B];
__device__ unsigned g_colmax[B];
__device__ float    g_diag[B];
__device__ unsigned g_done;

// Monotone float<->uint encoding (shifted): atomicMax(unsigned) == float max.
__device__ __forceinline__ unsigned enc2(float f) {
    unsigned u = __float_as_uint(f);
    return (u ^ ((unsigned)((int)u >> 31) | 0x80000000u)) - ENC_OFF;
}
__device__ __forceinline__ float dec2(unsigned e) {
    unsigned x = e + ENC_OFF;
    unsigned u = (x & 0x80000000u) ? (x ^ 0x80000000u) : ~x;
    return __uint_as_float(u);
}

// Scan body: each warp loads 8 rows per iteration -> 8 LDG.128 in flight
// (MLP_p1 = 8). 4 iterations cover TR=256 rows (8 warps x 8 rows x 4).
template<bool DIAG>
__device__ __forceinline__ void scan_body(const float* __restrict__ sim,
                                          int rowBase, int colBase,
                                          int tx, int ty, float* cm) {
    const int gcol = colBase + tx * 4;
    #pragma unroll
    for (int it = 0; it < TR / 64; it++) {
        const int grow = rowBase + it * 64 + ty * 8;
        const float* base = sim + (size_t)grow * B + gcol;

        float4 v[8];
        #pragma unroll
        for (int j = 0; j < 8; j++)        // 8 independent loads, front-batched
            v[j] = *reinterpret_cast<const float4*>(base + (size_t)j * B);

        if (DIAG) {
            #pragma unroll
            for (int j = 0; j < 8; j++) {
                const int gr = grow + j;
                if (gr == gcol + 0) { g_diag[gr] = v[j].x; v[j].x = NEG_INF; }
                if (gr == gcol + 1) { g_diag[gr] = v[j].y; v[j].y = NEG_INF; }
                if (gr == gcol + 2) { g_diag[gr] = v[j].z; v[j].z = NEG_INF; }
                if (gr == gcol + 3) { g_diag[gr] = v[j].w; v[j].w = NEG_INF; }
            }
        }

        #pragma unroll
        for (int j = 0; j < 8; j++) {
            cm[0] = fmaxf(cm[0], v[j].x);
            cm[1] = fmaxf(cm[1], v[j].y);
            cm[2] = fmaxf(cm[2], v[j].z);
            cm[3] = fmaxf(cm[3], v[j].w);
        }

        // Row maxes: 4 pairs, each reduced with 6 shuffles total.
        #pragma unroll
        for (int p = 0; p < 4; p++) {
            const float4 a = v[2 * p], b = v[2 * p + 1];
            float ra = fmaxf(fmaxf(a.x, a.y), fmaxf(a.z, a.w));
            float rb = fmaxf(fmaxf(b.x, b.y), fmaxf(b.z, b.w));
            ra = fmaxf(ra, __shfl_xor_sync(0xffffffffu, ra, 16));
            rb = fmaxf(rb, __shfl_xor_sync(0xffffffffu, rb, 16));
            float c = (tx < 16) ? ra : rb;
            #pragma unroll
            for (int o = 8; o > 0; o >>= 1)
                c = fmaxf(c, __shfl_xor_sync(0xffffffffu, c, o));
            // lane 0 holds row 2p's max; lane 16 holds row 2p+1's max.
            if (tx == 0)  atomicMax(&g_rowmax[grow + 2 * p],     enc2(c));
            if (tx == 16) atomicMax(&g_rowmax[grow + 2 * p + 1], enc2(c));
        }
    }
}

__global__ void __launch_bounds__(256, 5) wtl_fused(const float* __restrict__ sim,
                                                    float* __restrict__ out) {
    const int tx = threadIdx.x;            // 0..31
    const int ty = threadIdx.y;            // 0..7
    const int tid = ty * 32 + tx;
    const int colBase = blockIdx.x * TC;
    const int rowBase = blockIdx.y * TR;

    float cm[4];
    cm[0] = cm[1] = cm[2] = cm[3] = NEG_INF;

    // Diagonal intersects this tile iff bx/2 == by (TC=128, TR=256).
    if ((blockIdx.x >> 1) == blockIdx.y)
        scan_body<true >(sim, rowBase, colBase, tx, ty, cm);
    else
        scan_body<false>(sim, rowBase, colBase, tx, ty, cm);

    // Column-max: fold 8 warp-rows via shared, one RED.MAX per column.
    __shared__ float s_col[8][TC];
    *reinterpret_cast<float4*>(&s_col[ty][tx * 4]) =
        make_float4(cm[0], cm[1], cm[2], cm[3]);
    __syncthreads();

    if (tid < TC) {
        float m = s_col[0][tid];
        #pragma unroll
        for (int s = 1; s < 8; s++) m = fmaxf(m, s_col[s][tid]);
        atomicMax(&g_colmax[colBase + tid], enc2(m));
    }

    // ---- completion: last block computes the loss and resets scratch ----
    __shared__ unsigned s_last;
    __threadfence();
    __syncthreads();
    if (tid == 0) s_last = atomicAdd(&g_done, 1u);
    __syncthreads();
    if (s_last != NBLK - 1) return;
    __threadfence();   // acquire: see all other blocks' RED results

    float local = 0.0f;
    #pragma unroll 4
    for (int i = tid; i < B; i += 256) {
        const float rm  = dec2(__ldcg(&g_rowmax[i]));
        const float cx  = dec2(__ldcg(&g_colmax[i]));
        const float pos = __ldcg(&g_diag[i]);

        const float pos_loss = fmaxf(0.2f * pos * pos - 0.7f * pos + 0.5f, 0.0f);
        if (rm + 1.0f > pos)
            local += pos_loss + fmaxf(0.9f * rm * rm - 0.4f * rm + 0.03f, 0.0f);
        if (cx + 1.0f > pos)
            local += pos_loss + fmaxf(0.9f * cx * cx - 0.4f * cx + 0.03f, 0.0f);

        g_rowmax[i] = 0u;   // reset for next graph replay
        g_colmax[i] = 0u;
    }

    // deterministic block reduction (fixed tree)
    __shared__ float s_sum[256];
    s_sum[tid] = local;
    __syncthreads();
    #pragma unroll
    for (int s = 128; s > 0; s >>= 1) {
        if (tid < s) s_sum[tid] += s_sum[tid + s];
        __syncthreads();
    }
    if (tid == 0) {
        out[0] = s_sum[0] / (float)B;
        g_done = 0u;
    }
}

extern "C" void kernel_launch(void* const* d_in, const int* in_sizes, int n_in,
                              void* d_out, int out_size) {
    const float* sim = (const float*)d_in[0];
    float* out = (float*)d_out;

    dim3 grid(GX, GY);         // (64, 32)
    dim3 block(32, 8);
    wtl_fused<<<grid, block>>>(sim, out);
}

// round 6
// speedup vs baseline: 1.0469x; 1.0381x over previous
#include <cuda_runtime.h>
#include <cstdint>

#define B 8192
#define TC 128                 // tile cols (warp = 32 lanes x float4)
#define TR 256                 // tile rows
#define GX (B / TC)            // 64 col stripes
#define GY (B / TR)            // 32 row bands
#define NBLK (GX * GY)         // 2048
#define NFOLD 32               // last-N-blocks fold the partials

#define NEG_INF __int_as_float(0xff800000)

// Plain-STG scratch: fully overwritten every launch, no init kernel needed.
__device__ float    g_rowpart[GX * B];   // [col-stripe][row]  2 MB
__device__ float    g_colpart[GY * B];   // [row-band][col]    1 MB
__device__ float    g_diag[B];
__device__ float    g_blocksum[NFOLD];
__device__ unsigned g_done;              // zero-init; reset by final block
__device__ unsigned g_done2;

// ---------------------------------------------------------------------------
// Scan body == R1's proven K1 (73.5% DRAM): 1 LDG.128/lane/iter, unroll 4,
// 5-shuffle row reduce, plain STG partials. DIAG split from R3+.
// ---------------------------------------------------------------------------
template<bool DIAG>
__device__ __forceinline__ void scan_body(const float* __restrict__ sim,
                                          int rowBase, int colBase, int bx,
                                          int tx, int ty, float* cm) {
    const int gcol0 = colBase + tx * 4;
    #pragma unroll 4
    for (int r = ty; r < TR; r += 8) {
        const int grow = rowBase + r;
        const float4 v = *reinterpret_cast<const float4*>(
            sim + (size_t)grow * B + gcol0);

        float e0 = v.x, e1 = v.y, e2 = v.z, e3 = v.w;
        if (DIAG) {
            if (grow == gcol0 + 0) { g_diag[grow] = e0; e0 = NEG_INF; }
            if (grow == gcol0 + 1) { g_diag[grow] = e1; e1 = NEG_INF; }
            if (grow == gcol0 + 2) { g_diag[grow] = e2; e2 = NEG_INF; }
            if (grow == gcol0 + 3) { g_diag[grow] = e3; e3 = NEG_INF; }
        }

        cm[0] = fmaxf(cm[0], e0);
        cm[1] = fmaxf(cm[1], e1);
        cm[2] = fmaxf(cm[2], e2);
        cm[3] = fmaxf(cm[3], e3);

        float rmax = fmaxf(fmaxf(e0, e1), fmaxf(e2, e3));
        #pragma unroll
        for (int o = 16; o > 0; o >>= 1)
            rmax = fmaxf(rmax, __shfl_xor_sync(0xffffffffu, rmax, o));
        if (tx == 0)
            g_rowpart[(size_t)bx * B + grow] = rmax;   // plain STG, no atomic
    }
}

__global__ void __launch_bounds__(256) wtl_fused(const float* __restrict__ sim,
                                                 float* __restrict__ out) {
    const int tx = threadIdx.x;            // 0..31
    const int ty = threadIdx.y;            // 0..7
    const int tid = ty * 32 + tx;
    const int colBase = blockIdx.x * TC;
    const int rowBase = blockIdx.y * TR;

    float cm[4];
    cm[0] = cm[1] = cm[2] = cm[3] = NEG_INF;

    // Diagonal intersects this tile iff bx/2 == by (TC=128, TR=256).
    if ((blockIdx.x >> 1) == blockIdx.y)
        scan_body<true >(sim, rowBase, colBase, blockIdx.x, tx, ty, cm);
    else
        scan_body<false>(sim, rowBase, colBase, blockIdx.x, tx, ty, cm);

    // Column-max: fold 8 warp-rows via shared, plain STG per column.
    __shared__ float s_col[8][TC];
    *reinterpret_cast<float4*>(&s_col[ty][tx * 4]) =
        make_float4(cm[0], cm[1], cm[2], cm[3]);
    __syncthreads();

    if (tid < TC) {
        float m = s_col[0][tid];
        #pragma unroll
        for (int s = 1; s < 8; s++) m = fmaxf(m, s_col[s][tid]);
        g_colpart[(size_t)blockIdx.y * B + colBase + tid] = m;
    }

    // ---- completion protocol: last NFOLD arrivals fold the partials ----
    __shared__ unsigned s_last;
    __threadfence();                       // publish partial STGs
    __syncthreads();
    if (tid == 0) s_last = atomicAdd(&g_done, 1u);
    __syncthreads();
    if (s_last < NBLK - NFOLD) return;
    const int o = (int)s_last - (NBLK - NFOLD);   // unique 0..NFOLD-1

    // Wait until ALL blocks have published (≤31 stragglers remain running;
    // plenty of free SM slots, no deadlock possible).
    if (tid == 0) {
        while (*(volatile unsigned*)&g_done != NBLK) __nanosleep(64);
    }
    __syncthreads();
    __threadfence();                       // acquire all partials

    // Fold slice [o*256, o*256+256): 64 row-stripes + 32 col-bands per index.
    {
        const int i = o * 256 + tid;
        float rm = NEG_INF;
        #pragma unroll 8
        for (int s = 0; s < GX; s++)
            rm = fmaxf(rm, __ldcg(&g_rowpart[(size_t)s * B + i]));
        float cx = NEG_INF;
        #pragma unroll 8
        for (int s = 0; s < GY; s++)
            cx = fmaxf(cx, __ldcg(&g_colpart[(size_t)s * B + i]));
        const float pos = __ldcg(&g_diag[i]);

        const float pos_loss = fmaxf(0.2f * pos * pos - 0.7f * pos + 0.5f, 0.0f);
        float local = 0.0f;
        if (rm + 1.0f > pos)
            local += pos_loss + fmaxf(0.9f * rm * rm - 0.4f * rm + 0.03f, 0.0f);
        if (cx + 1.0f > pos)
            local += pos_loss + fmaxf(0.9f * cx * cx - 0.4f * cx + 0.03f, 0.0f);

        __shared__ float s_sum[256];
        s_sum[tid] = local;
        __syncthreads();
        #pragma unroll
        for (int s = 128; s > 0; s >>= 1) {
            if (tid < s) s_sum[tid] += s_sum[tid + s];
            __syncthreads();
        }
        if (tid == 0) g_blocksum[o] = s_sum[0];
    }

    // Final: last of the NFOLD fold-blocks sums the slice results.
    __shared__ unsigned s_last2;
    __threadfence();
    __syncthreads();
    if (tid == 0) s_last2 = atomicAdd(&g_done2, 1u);
    __syncthreads();
    if (s_last2 != NFOLD - 1) return;
    __threadfence();                       // acquire g_blocksum

    if (tid < 32) {
        float v = g_blocksum[tid];         // NFOLD == 32
        #pragma unroll
        for (int off = 16; off > 0; off >>= 1)
            v += __shfl_xor_sync(0xffffffffu, v, off);
        if (tid == 0) {
            out[0] = v / (float)B;
            g_done  = 0u;                  // reset for next graph replay
            g_done2 = 0u;
        }
    }
}

extern "C" void kernel_launch(void* const* d_in, const int* in_sizes, int n_in,
                              void* d_out, int out_size) {
    const float* sim = (const float*)d_in[0];
    float* out = (float*)d_out;

    dim3 grid(GX, GY);         // (64, 32)
    dim3 block(32, 8);
    wtl_fused<<<grid, block>>>(sim, out);
}

// round 7
// speedup vs baseline: 1.0730x; 1.0250x over previous
#include <cuda_runtime.h>
#include <cstdint>

#define B 8192
#define TC 128                 // tile cols (warp = 32 lanes x float4)
#define TR 256                 // tile rows
#define GX (B / TC)            // 64 col stripes
#define GY (B / TR)            // 32 row bands
#define NBLK (GX * GY)         // 2048
#define NFOLD 32               // last-N-blocks fold the partials

#define NEG_INF __int_as_float(0xff800000)

// Plain-STG scratch: fully overwritten every launch, no init kernel needed.
__device__ float    g_rowpart[GX * B];   // [col-stripe][row]  2 MB
__device__ float    g_colpart[GY * B];   // [row-band][col]    1 MB
__device__ float    g_diag[B];
__device__ float    g_blocksum[NFOLD];
__device__ unsigned g_done;              // zero-init; reset by final block
__device__ unsigned g_done2;

__device__ __forceinline__ void fence_gpu() {
    asm volatile("fence.acq_rel.gpu;" ::: "memory");
}

// ---------------------------------------------------------------------------
// Scan body == R1's proven K1 (73.5% DRAM): 1 LDG.128/lane/iter, unroll 4,
// 5-shuffle row reduce, plain STG partials.
// ---------------------------------------------------------------------------
template<bool DIAG>
__device__ __forceinline__ void scan_body(const float* __restrict__ sim,
                                          int rowBase, int colBase, int bx,
                                          int tx, int ty, float* cm) {
    const int gcol0 = colBase + tx * 4;
    #pragma unroll 4
    for (int r = ty; r < TR; r += 8) {
        const int grow = rowBase + r;
        const float4 v = *reinterpret_cast<const float4*>(
            sim + (size_t)grow * B + gcol0);

        float e0 = v.x, e1 = v.y, e2 = v.z, e3 = v.w;
        if (DIAG) {
            if (grow == gcol0 + 0) { g_diag[grow] = e0; e0 = NEG_INF; }
            if (grow == gcol0 + 1) { g_diag[grow] = e1; e1 = NEG_INF; }
            if (grow == gcol0 + 2) { g_diag[grow] = e2; e2 = NEG_INF; }
            if (grow == gcol0 + 3) { g_diag[grow] = e3; e3 = NEG_INF; }
        }

        cm[0] = fmaxf(cm[0], e0);
        cm[1] = fmaxf(cm[1], e1);
        cm[2] = fmaxf(cm[2], e2);
        cm[3] = fmaxf(cm[3], e3);

        float rmax = fmaxf(fmaxf(e0, e1), fmaxf(e2, e3));
        #pragma unroll
        for (int o = 16; o > 0; o >>= 1)
            rmax = fmaxf(rmax, __shfl_xor_sync(0xffffffffu, rmax, o));
        if (tx == 0)
            g_rowpart[(size_t)bx * B + grow] = rmax;   // plain STG, no atomic
    }
}

__global__ void __launch_bounds__(256) wtl_fused(const float* __restrict__ sim,
                                                 float* __restrict__ out) {
    const int tx = threadIdx.x;            // 0..31
    const int ty = threadIdx.y;            // 0..7
    const int tid = ty * 32 + tx;
    const int colBase = blockIdx.x * TC;
    const int rowBase = blockIdx.y * TR;

    float cm[4];
    cm[0] = cm[1] = cm[2] = cm[3] = NEG_INF;

    // Diagonal intersects this tile iff bx/2 == by (TC=128, TR=256).
    if ((blockIdx.x >> 1) == blockIdx.y)
        scan_body<true >(sim, rowBase, colBase, blockIdx.x, tx, ty, cm);
    else
        scan_body<false>(sim, rowBase, colBase, blockIdx.x, tx, ty, cm);

    // Column-max: fold 8 warp-rows via shared, plain STG per column.
    __shared__ float s_col[8][TC];
    *reinterpret_cast<float4*>(&s_col[ty][tx * 4]) =
        make_float4(cm[0], cm[1], cm[2], cm[3]);
    __syncthreads();

    if (tid < TC) {
        float m = s_col[0][tid];
        #pragma unroll
        for (int s = 1; s < 8; s++) m = fmaxf(m, s_col[s][tid]);
        g_colpart[(size_t)blockIdx.y * B + colBase + tid] = m;
    }

    // ---- completion protocol: last NFOLD arrivals fold the partials ----
    // Single-thread cumulative fence: __syncthreads() orders all threads'
    // STGs before tid 0's fence; fence.acq_rel.gpu is cumulative, so one
    // fence publishes the whole block's stores. (R6 had 256 fences/block
    // = 524K gpu-scope MEMBARs — the hypothesized 18us tail.)
    __shared__ unsigned s_last;
    __syncthreads();
    if (tid == 0) {
        fence_gpu();
        s_last = atomicAdd(&g_done, 1u);
    }
    __syncthreads();
    if (s_last < NBLK - NFOLD) return;
    const int o = (int)s_last - (NBLK - NFOLD);   // unique 0..NFOLD-1

    // Wait until ALL blocks have published.
    if (tid == 0) {
        while (*(volatile unsigned*)&g_done != NBLK) __nanosleep(64);
        fence_gpu();                      // acquire all partials (cumulative)
    }
    __syncthreads();

    // Fold slice [o*256, o*256+256): 64 row-stripes + 32 col-bands per index.
    {
        const int i = o * 256 + tid;
        float rm = NEG_INF;
        #pragma unroll 8
        for (int s = 0; s < GX; s++)
            rm = fmaxf(rm, __ldcg(&g_rowpart[(size_t)s * B + i]));
        float cx = NEG_INF;
        #pragma unroll 8
        for (int s = 0; s < GY; s++)
            cx = fmaxf(cx, __ldcg(&g_colpart[(size_t)s * B + i]));
        const float pos = __ldcg(&g_diag[i]);

        const float pos_loss = fmaxf(0.2f * pos * pos - 0.7f * pos + 0.5f, 0.0f);
        float local = 0.0f;
        if (rm + 1.0f > pos)
            local += pos_loss + fmaxf(0.9f * rm * rm - 0.4f * rm + 0.03f, 0.0f);
        if (cx + 1.0f > pos)
            local += pos_loss + fmaxf(0.9f * cx * cx - 0.4f * cx + 0.03f, 0.0f);

        __shared__ float s_sum[256];
        s_sum[tid] = local;
        __syncthreads();
        #pragma unroll
        for (int s = 128; s > 0; s >>= 1) {
            if (tid < s) s_sum[tid] += s_sum[tid + s];
            __syncthreads();
        }
        if (tid == 0) g_blocksum[o] = s_sum[0];
    }

    // Final: last of the NFOLD fold-blocks sums the slice results.
    __shared__ unsigned s_last2;
    __syncthreads();
    if (tid == 0) {
        fence_gpu();
        s_last2 = atomicAdd(&g_done2, 1u);
    }
    __syncthreads();
    if (s_last2 != NFOLD - 1) return;
    if (tid == 0) fence_gpu();            // acquire g_blocksum
    __syncthreads();

    if (tid < 32) {
        float v = g_blocksum[tid];         // NFOLD == 32
        #pragma unroll
        for (int off = 16; off > 0; off >>= 1)
            v += __shfl_xor_sync(0xffffffffu, v, off);
        if (tid == 0) {
            out[0] = v / (float)B;
            g_done  = 0u;                  // reset for next graph replay
            g_done2 = 0u;
        }
    }
}

extern "C" void kernel_launch(void* const* d_in, const int* in_sizes, int n_in,
                              void* d_out, int out_size) {
    const float* sim = (const float*)d_in[0];
    float* out = (float*)d_out;

    dim3 grid(GX, GY);         // (64, 32)
    dim3 block(32, 8);
    wtl_fused<<<grid, block>>>(sim, out);
}

// round 8
// speedup vs baseline: 1.0736x; 1.0005x over previous
#include <cuda_runtime.h>
#include <cstdint>

#define B 8192
#define TC 128                 // tile cols (warp = 32 lanes x float4)
#define TR 256                 // tile rows
#define GX (B / TC)            // 64 col stripes
#define GY (B / TR)            // 32 row bands
#define K2_BLOCKS 32

#define NEG_INF __int_as_float(0xff800000)

// Scratch: fully overwritten every launch (no init kernel needed).
__device__ float    g_rowpart[GX * B];   // [col-stripe][row]  2 MB
__device__ float    g_colpart[GY * B];   // [row-band][col]    1 MB
__device__ float    g_diag[B];
__device__ float    g_blocksum[K2_BLOCKS];
__device__ unsigned g_done;              // zero-init; reset by K2 finisher

// ---------------------------------------------------------------------------
// K1: R1's proven scan (47.1us, 73.5% DRAM). One LDG.128 per lane per iter,
// unroll 4, 5-shuffle row reduce, plain STG partials. Diagonal handling
// template-split: only 4/2048 blocks run the predicated path.
// ---------------------------------------------------------------------------
template<bool DIAG>
__device__ __forceinline__ void scan_body(const float* __restrict__ sim,
                                          int rowBase, int colBase, int bx,
                                          int tx, int ty, float* cm) {
    const int gcol0 = colBase + tx * 4;
    #pragma unroll 4
    for (int r = ty; r < TR; r += 8) {
        const int grow = rowBase + r;
        const float4 v = *reinterpret_cast<const float4*>(
            sim + (size_t)grow * B + gcol0);

        float e0 = v.x, e1 = v.y, e2 = v.z, e3 = v.w;
        if (DIAG) {
            if (grow == gcol0 + 0) { g_diag[grow] = e0; e0 = NEG_INF; }
            if (grow == gcol0 + 1) { g_diag[grow] = e1; e1 = NEG_INF; }
            if (grow == gcol0 + 2) { g_diag[grow] = e2; e2 = NEG_INF; }
            if (grow == gcol0 + 3) { g_diag[grow] = e3; e3 = NEG_INF; }
        }

        cm[0] = fmaxf(cm[0], e0);
        cm[1] = fmaxf(cm[1], e1);
        cm[2] = fmaxf(cm[2], e2);
        cm[3] = fmaxf(cm[3], e3);

        float rmax = fmaxf(fmaxf(e0, e1), fmaxf(e2, e3));
        #pragma unroll
        for (int o = 16; o > 0; o >>= 1)
            rmax = fmaxf(rmax, __shfl_xor_sync(0xffffffffu, rmax, o));
        if (tx == 0)
            g_rowpart[(size_t)bx * B + grow] = rmax;
    }
}

__global__ void __launch_bounds__(256) wtl_k1(const float* __restrict__ sim) {
    const int tx = threadIdx.x;            // 0..31
    const int ty = threadIdx.y;            // 0..7
    const int tid = ty * 32 + tx;
    const int colBase = blockIdx.x * TC;
    const int rowBase = blockIdx.y * TR;

    float cm[4];
    cm[0] = cm[1] = cm[2] = cm[3] = NEG_INF;

    // Diagonal intersects this tile iff bx/2 == by (TC=128, TR=256).
    if ((blockIdx.x >> 1) == blockIdx.y)
        scan_body<true >(sim, rowBase, colBase, blockIdx.x, tx, ty, cm);
    else
        scan_body<false>(sim, rowBase, colBase, blockIdx.x, tx, ty, cm);

    // Column-max: fold 8 warp-rows via shared, plain STG per column.
    __shared__ float s_col[8][TC];
    *reinterpret_cast<float4*>(&s_col[ty][tx * 4]) =
        make_float4(cm[0], cm[1], cm[2], cm[3]);
    __syncthreads();

    if (tid < TC) {
        float m = s_col[0][tid];
        #pragma unroll
        for (int s = 1; s < 8; s++) m = fmaxf(m, s_col[s][tid]);
        g_colpart[(size_t)blockIdx.y * B + colBase + tid] = m;
    }
}

// ---------------------------------------------------------------------------
// K2: fold partials + loss + finisher in ONE kernel. 32 blocks x 256 threads;
// index i = blockIdx.x*256 + tid. Last-arriving block sums the 32 block sums
// and writes the scalar (replaces R1's separate K3 = 4.1us of launch/drain).
// ---------------------------------------------------------------------------
__global__ void __launch_bounds__(256) wtl_k2(float* __restrict__ out) {
    const int tid = threadIdx.x;
    const int i = blockIdx.x * 256 + tid;

    float rm = NEG_INF;
    #pragma unroll 8
    for (int s = 0; s < GX; s++)
        rm = fmaxf(rm, g_rowpart[(size_t)s * B + i]);

    float cx = NEG_INF;
    #pragma unroll 8
    for (int s = 0; s < GY; s++)
        cx = fmaxf(cx, g_colpart[(size_t)s * B + i]);

    const float pos = g_diag[i];
    const float pos_loss = fmaxf(0.2f * pos * pos - 0.7f * pos + 0.5f, 0.0f);

    float local = 0.0f;
    if (rm + 1.0f > pos)
        local += pos_loss + fmaxf(0.9f * rm * rm - 0.4f * rm + 0.03f, 0.0f);
    if (cx + 1.0f > pos)
        local += pos_loss + fmaxf(0.9f * cx * cx - 0.4f * cx + 0.03f, 0.0f);

    // deterministic block reduction (fixed tree)
    __shared__ float s_sum[256];
    s_sum[tid] = local;
    __syncthreads();
    #pragma unroll
    for (int s = 128; s > 0; s >>= 1) {
        if (tid < s) s_sum[tid] += s_sum[tid + s];
        __syncthreads();
    }

    // publish block sum; last arrival finishes.
    __shared__ unsigned s_last;
    if (tid == 0) {
        g_blocksum[blockIdx.x] = s_sum[0];
        __threadfence();
        s_last = atomicAdd(&g_done, 1u);
    }
    __syncthreads();
    if (s_last != K2_BLOCKS - 1) return;
    if (tid == 0) __threadfence();         // acquire all block sums
    __syncthreads();

    if (tid < 32) {
        float v = g_blocksum[tid];         // K2_BLOCKS == 32
        #pragma unroll
        for (int o = 16; o > 0; o >>= 1)
            v += __shfl_xor_sync(0xffffffffu, v, o);
        if (tid == 0) {
            out[0] = v / (float)B;
            g_done = 0u;                   // reset for next graph replay
        }
    }
}

extern "C" void kernel_launch(void* const* d_in, const int* in_sizes, int n_in,
                              void* d_out, int out_size) {
    const float* sim = (const float*)d_in[0];
    float* out = (float*)d_out;

    dim3 grid1(GX, GY);        // (64, 32)
    dim3 block1(32, 8);
    wtl_k1<<<grid1, block1>>>(sim);
    wtl_k2<<<K2_BLOCKS, 256>>>(out);
}

// round 9
// speedup vs baseline: 1.1884x; 1.1069x over previous
#include <cuda_runtime.h>
#include <cstdint>

#define B 8192
#define TC 128                 // tile cols (warp = 32 lanes x float4)
#define TR 256                 // tile rows
#define GX (B / TC)            // 64 col stripes
#define GY (B / TR)            // 32 row bands
#define K2_BLOCKS 256          // 32 indices per block, 8 warps fold stripes

#define NEG_INF __int_as_float(0xff800000)

// Scratch: fully overwritten every launch (no init kernel needed).
__device__ float    g_rowpart[GX * B];   // [col-stripe][row]  2 MB
__device__ float    g_colpart[GY * B];   // [row-band][col]    1 MB
__device__ float    g_diag[B];
__device__ float    g_blocksum[K2_BLOCKS];
__device__ unsigned g_done;              // zero-init; reset by K2 finisher

// ---------------------------------------------------------------------------
// K1: R1's proven scan (47.1us, 73.5% DRAM). UNCHANGED from R8.
// ---------------------------------------------------------------------------
template<bool DIAG>
__device__ __forceinline__ void scan_body(const float* __restrict__ sim,
                                          int rowBase, int colBase, int bx,
                                          int tx, int ty, float* cm) {
    const int gcol0 = colBase + tx * 4;
    #pragma unroll 4
    for (int r = ty; r < TR; r += 8) {
        const int grow = rowBase + r;
        const float4 v = *reinterpret_cast<const float4*>(
            sim + (size_t)grow * B + gcol0);

        float e0 = v.x, e1 = v.y, e2 = v.z, e3 = v.w;
        if (DIAG) {
            if (grow == gcol0 + 0) { g_diag[grow] = e0; e0 = NEG_INF; }
            if (grow == gcol0 + 1) { g_diag[grow] = e1; e1 = NEG_INF; }
            if (grow == gcol0 + 2) { g_diag[grow] = e2; e2 = NEG_INF; }
            if (grow == gcol0 + 3) { g_diag[grow] = e3; e3 = NEG_INF; }
        }

        cm[0] = fmaxf(cm[0], e0);
        cm[1] = fmaxf(cm[1], e1);
        cm[2] = fmaxf(cm[2], e2);
        cm[3] = fmaxf(cm[3], e3);

        float rmax = fmaxf(fmaxf(e0, e1), fmaxf(e2, e3));
        #pragma unroll
        for (int o = 16; o > 0; o >>= 1)
            rmax = fmaxf(rmax, __shfl_xor_sync(0xffffffffu, rmax, o));
        if (tx == 0)
            g_rowpart[(size_t)bx * B + grow] = rmax;
    }
}

__global__ void __launch_bounds__(256) wtl_k1(const float* __restrict__ sim) {
    const int tx = threadIdx.x;            // 0..31
    const int ty = threadIdx.y;            // 0..7
    const int tid = ty * 32 + tx;
    const int colBase = blockIdx.x * TC;
    const int rowBase = blockIdx.y * TR;

    float cm[4];
    cm[0] = cm[1] = cm[2] = cm[3] = NEG_INF;

    if ((blockIdx.x >> 1) == blockIdx.y)
        scan_body<true >(sim, rowBase, colBase, blockIdx.x, tx, ty, cm);
    else
        scan_body<false>(sim, rowBase, colBase, blockIdx.x, tx, ty, cm);

    __shared__ float s_col[8][TC];
    *reinterpret_cast<float4*>(&s_col[ty][tx * 4]) =
        make_float4(cm[0], cm[1], cm[2], cm[3]);
    __syncthreads();

    if (tid < TC) {
        float m = s_col[0][tid];
        #pragma unroll
        for (int s = 1; s < 8; s++) m = fmaxf(m, s_col[s][tid]);
        g_colpart[(size_t)blockIdx.y * B + colBase + tid] = m;
    }
}

// ---------------------------------------------------------------------------
// K2: parallel fold. Block b owns indices [b*32, b*32+32). Warp w loads
// stripe subset {w, w+8, ...}: 8 row + 4 col coalesced 128B loads per thread,
// front-batched. Shared fold across warps, loss on warp 0, last block sums.
// ---------------------------------------------------------------------------
__global__ void __launch_bounds__(256) wtl_k2(float* __restrict__ out) {
    const int lane = threadIdx.x & 31;
    const int w    = threadIdx.x >> 5;     // 0..7
    const int i    = blockIdx.x * 32 + lane;

    float r[8], c[4];
    #pragma unroll
    for (int k = 0; k < 8; k++)            // row stripes w, w+8, ..., w+56
        r[k] = g_rowpart[(size_t)(w + k * 8) * B + i];
    #pragma unroll
    for (int k = 0; k < 4; k++)            // col bands  w, w+8, w+16, w+24
        c[k] = g_colpart[(size_t)(w + k * 8) * B + i];

    float rm = r[0], cx = c[0];
    #pragma unroll
    for (int k = 1; k < 8; k++) rm = fmaxf(rm, r[k]);
    #pragma unroll
    for (int k = 1; k < 4; k++) cx = fmaxf(cx, c[k]);

    __shared__ float s_r[8][32];
    __shared__ float s_c[8][32];
    s_r[w][lane] = rm;
    s_c[w][lane] = cx;
    __syncthreads();

    __shared__ float s_blk;
    if (w == 0) {
        float rmax = s_r[0][lane], cmax = s_c[0][lane];
        #pragma unroll
        for (int k = 1; k < 8; k++) {
            rmax = fmaxf(rmax, s_r[k][lane]);
            cmax = fmaxf(cmax, s_c[k][lane]);
        }
        const float pos = g_diag[i];
        const float pos_loss = fmaxf(0.2f * pos * pos - 0.7f * pos + 0.5f, 0.0f);

        float local = 0.0f;
        if (rmax + 1.0f > pos)
            local += pos_loss + fmaxf(0.9f * rmax * rmax - 0.4f * rmax + 0.03f, 0.0f);
        if (cmax + 1.0f > pos)
            local += pos_loss + fmaxf(0.9f * cmax * cmax - 0.4f * cmax + 0.03f, 0.0f);

        #pragma unroll
        for (int o = 16; o > 0; o >>= 1)
            local += __shfl_xor_sync(0xffffffffu, local, o);
        if (lane == 0) s_blk = local;
    }
    __syncthreads();

    // publish block sum; last-arriving block finishes.
    __shared__ unsigned s_last;
    if (threadIdx.x == 0) {
        g_blocksum[blockIdx.x] = s_blk;
        __threadfence();
        s_last = atomicAdd(&g_done, 1u);
    }
    __syncthreads();
    if (s_last != K2_BLOCKS - 1) return;
    if (threadIdx.x == 0) __threadfence();   // acquire all block sums
    __syncthreads();

    // deterministic fixed-tree fold of 256 block sums
    __shared__ float s_f[256];
    s_f[threadIdx.x] = g_blocksum[threadIdx.x];
    __syncthreads();
    #pragma unroll
    for (int s = 128; s > 0; s >>= 1) {
        if (threadIdx.x < s) s_f[threadIdx.x] += s_f[threadIdx.x + s];
        __syncthreads();
    }
    if (threadIdx.x == 0) {
        out[0] = s_f[0] / (float)B;
        g_done = 0u;                        // reset for next graph replay
    }
}

extern "C" void kernel_launch(void* const* d_in, const int* in_sizes, int n_in,
                              void* d_out, int out_size) {
    const float* sim = (const float*)d_in[0];
    float* out = (float*)d_out;

    dim3 grid1(GX, GY);        // (64, 32)
    dim3 block1(32, 8);
    wtl_k1<<<grid1, block1>>>(sim);
    wtl_k2<<<K2_BLOCKS, 256>>>(out);
}

// round 10
// speedup vs baseline: 1.3465x; 1.1331x over previous
#include <cuda_runtime.h>
#include <cstdint>

#define B 8192
#define TC 128                 // tile cols (warp = 32 lanes x float4)
#define TR 256                 // tile rows
#define GX (B / TC)            // 64 col stripes
#define GY (B / TR)            // 32 row bands
#define K2_BLOCKS 64

#define NEG_INF __int_as_float(0xff800000)
#define ENC_OFF 0x007FFFFFu    // shifted so enc2(-inf) == 0 (zero-init scratch)

// Final max arrays (zero-init == enc(-inf); K2 resets them after reading).
__device__ unsigned g_rowmax[B];         // 32 KB
__device__ unsigned g_colmax[B];         // 32 KB
__device__ float    g_diag[B];
__device__ float    g_blocksum[K2_BLOCKS];
__device__ unsigned g_done;              // zero-init; reset by K2 finisher

// Monotone float<->uint encoding (shifted): atomicMax(unsigned) == float max.
__device__ __forceinline__ unsigned enc2(float f) {
    unsigned u = __float_as_uint(f);
    return (u ^ ((unsigned)((int)u >> 31) | 0x80000000u)) - ENC_OFF;
}
__device__ __forceinline__ float dec2(unsigned e) {
    unsigned x = e + ENC_OFF;
    unsigned u = (x & 0x80000000u) ? (x ^ 0x80000000u) : ~x;
    return __uint_as_float(u);
}

// ---------------------------------------------------------------------------
// K1: proven scan loop (73.5% DRAM), but row maxes go to SHARED (STS by
// lane 0), and all global atomics happen once at block drain: 256 row +
// 128 col atomicMax into the final 64 KB arrays. No partial arrays at all.
// ---------------------------------------------------------------------------
template<bool DIAG>
__device__ __forceinline__ void scan_body(const float* __restrict__ sim,
                                          int rowBase, int colBase,
                                          int tx, int ty, float* cm,
                                          float (*s_row)) {
    const int gcol0 = colBase + tx * 4;
    #pragma unroll 4
    for (int r = ty; r < TR; r += 8) {
        const int grow = rowBase + r;
        const float4 v = *reinterpret_cast<const float4*>(
            sim + (size_t)grow * B + gcol0);

        float e0 = v.x, e1 = v.y, e2 = v.z, e3 = v.w;
        if (DIAG) {
            if (grow == gcol0 + 0) { g_diag[grow] = e0; e0 = NEG_INF; }
            if (grow == gcol0 + 1) { g_diag[grow] = e1; e1 = NEG_INF; }
            if (grow == gcol0 + 2) { g_diag[grow] = e2; e2 = NEG_INF; }
            if (grow == gcol0 + 3) { g_diag[grow] = e3; e3 = NEG_INF; }
        }

        cm[0] = fmaxf(cm[0], e0);
        cm[1] = fmaxf(cm[1], e1);
        cm[2] = fmaxf(cm[2], e2);
        cm[3] = fmaxf(cm[3], e3);

        float rmax = fmaxf(fmaxf(e0, e1), fmaxf(e2, e3));
        #pragma unroll
        for (int o = 16; o > 0; o >>= 1)
            rmax = fmaxf(rmax, __shfl_xor_sync(0xffffffffu, rmax, o));
        if (tx == 0)
            s_row[r] = rmax;               // STS, not STG
    }
}

__global__ void __launch_bounds__(256) wtl_k1(const float* __restrict__ sim) {
    const int tx = threadIdx.x;            // 0..31
    const int ty = threadIdx.y;            // 0..7
    const int tid = ty * 32 + tx;
    const int colBase = blockIdx.x * TC;
    const int rowBase = blockIdx.y * TR;

    __shared__ float s_row[TR];            // 1 KB
    __shared__ float s_col[8][TC];         // 4 KB

    float cm[4];
    cm[0] = cm[1] = cm[2] = cm[3] = NEG_INF;

    // Diagonal intersects this tile iff bx/2 == by (TC=128, TR=256).
    if ((blockIdx.x >> 1) == blockIdx.y)
        scan_body<true >(sim, rowBase, colBase, tx, ty, cm, s_row);
    else
        scan_body<false>(sim, rowBase, colBase, tx, ty, cm, s_row);

    *reinterpret_cast<float4*>(&s_col[ty][tx * 4]) =
        make_float4(cm[0], cm[1], cm[2], cm[3]);
    __syncthreads();

    // Drain-phase atomics: 256 row + 128 col atomicMax per block.
    atomicMax(&g_rowmax[rowBase + tid], enc2(s_row[tid]));

    if (tid < TC) {
        float m = s_col[0][tid];
        #pragma unroll
        for (int s = 1; s < 8; s++) m = fmaxf(m, s_col[s][tid]);
        atomicMax(&g_colmax[colBase + tid], enc2(m));
    }
}

// ---------------------------------------------------------------------------
// K2: tiny finisher. 64 blocks x 128 threads = 8192 indices, one each.
// Reads 96 KB total, computes losses, fixed-tree reduce, last block sums
// and resets scratch for the next graph replay.
// ---------------------------------------------------------------------------
__global__ void __launch_bounds__(128) wtl_k2(float* __restrict__ out) {
    const int tid = threadIdx.x;
    const int i = blockIdx.x * 128 + tid;

    const float rm  = dec2(g_rowmax[i]);
    const float cx  = dec2(g_colmax[i]);
    const float pos = g_diag[i];

    g_rowmax[i] = 0u;                      // reset for next replay
    g_colmax[i] = 0u;

    const float pos_loss = fmaxf(0.2f * pos * pos - 0.7f * pos + 0.5f, 0.0f);
    float local = 0.0f;
    if (rm + 1.0f > pos)
        local += pos_loss + fmaxf(0.9f * rm * rm - 0.4f * rm + 0.03f, 0.0f);
    if (cx + 1.0f > pos)
        local += pos_loss + fmaxf(0.9f * cx * cx - 0.4f * cx + 0.03f, 0.0f);

    // deterministic fixed-tree block reduction
    __shared__ float s_sum[128];
    s_sum[tid] = local;
    __syncthreads();
    #pragma unroll
    for (int s = 64; s > 0; s >>= 1) {
        if (tid < s) s_sum[tid] += s_sum[tid + s];
        __syncthreads();
    }

    // publish; last-arriving block finishes.
    __shared__ unsigned s_last;
    if (tid == 0) {
        g_blocksum[blockIdx.x] = s_sum[0];
        __threadfence();
        s_last = atomicAdd(&g_done, 1u);
    }
    __syncthreads();
    if (s_last != K2_BLOCKS - 1) return;
    if (tid == 0) __threadfence();         // acquire all block sums
    __syncthreads();

    if (tid < 32) {
        float v = g_blocksum[tid] + g_blocksum[tid + 32];  // 64 sums
        #pragma unroll
        for (int o = 16; o > 0; o >>= 1)
            v += __shfl_xor_sync(0xffffffffu, v, o);
        if (tid == 0) {
            out[0] = v / (float)B;
            g_done = 0u;                   // reset for next replay
        }
    }
}

extern "C" void kernel_launch(void* const* d_in, const int* in_sizes, int n_in,
                              void* d_out, int out_size) {
    const float* sim = (const float*)d_in[0];
    float* out = (float*)d_out;

    dim3 grid1(GX, GY);        // (64, 32)
    dim3 block1(32, 8);
    wtl_k1<<<grid1, block1>>>(sim);
    wtl_k2<<<K2_BLOCKS, 128>>>(out);
}